// round 5
// baseline (speedup 1.0000x reference)
#include <cuda_runtime.h>
#include <math.h>

#define BE 64
#define NOCT 32
#define NSAMP 32768
#define TPB 256
#define ITEM_SAMP 1024
#define NITEMS (BE * NSAMP / ITEM_SAMP)   // 2048 work items
#define SPT 4                             // samples per thread per item

// Scratch (no allocation allowed). g_wmax: each slot written exactly once per
// launch (queue guarantees unique claim). g_ctr: reset to 0 by norm_kernel,
// which always runs after osc_kernel in-stream -> deterministic across
// graph replays (static zero-init covers the very first launch).
__device__ float g_wmax[NITEMS];
__device__ int   g_ctr;

// ---------------------------------------------------------------------------
// Kernel A: oscillator bank with work-stealing queue.
// Item = (be, chunk of 1024 samples). Octave loop outer, 4 independent
// per-thread sample chains inner. Phase math replicates the reference's f32
// rounding exactly (separate RN ops, sequential cumsum, fl32(f*t) phase).
// ---------------------------------------------------------------------------
__global__ void __launch_bounds__(TPB)
osc_kernel(const float* __restrict__ f0_in,
           const float* __restrict__ dec_in,
           const float* __restrict__ sp_in,
           float* __restrict__ out) {
    __shared__ float sf[BE * NOCT];
    __shared__ float sa[BE * NOCT];
    __shared__ int   snact[BE];
    __shared__ int   s_item;
    __shared__ float wm[TPB / 32];

    const int tid  = threadIdx.x;
    const int lane = tid & 31;
    const int wrp  = tid >> 5;

    // ---- one-time per-block param table for all 64 be ----
    if (tid < BE) {
        const float MINF   = (float)(20.0 / 11025.0);
        const float FRANGE = (float)(3000.0 / 11025.0 - 20.0 / 11025.0);
        const float PI_F   = (float)3.14159265358979323846;
        const float RESF   = (float)((1.0 - 0.01) * 0.99);

        float f0  = fabsf(f0_in[tid]);
        float fsc = __fmul_rn(__fadd_rn(MINF, __fmul_rn(f0, FRANGE)), PI_F);
        float sp  = sp_in[tid];

        float x  = dec_in[tid];
        float s1 = 1.0f / (1.0f + expf(-x));
        float s2 = 1.0f / (1.0f + expf(-s1));
        float d  = __fadd_rn(0.01f, __fmul_rn(s2, RESF));
        float ld = logf(__fadd_rn(d, 1e-12f));

        float fac = 0.0f, cl = 0.0f;
        int nact = 0;
        #pragma unroll 1
        for (int o = 0; o < NOCT; o++) {
            fac = __fadd_rn(fac, sp);          // sequential f32 cumsum
            cl  = __fadd_rn(cl, ld);
            float f0s = __fmul_rn(fsc, fac);
            sf[tid * NOCT + o] = f0s;
            sa[tid * NOCT + o] = expf(cl);
            if (f0s < 1.0f) nact = o + 1;      // monotone -> prefix mask
        }
        snact[tid] = nact;
    }
    __syncthreads();

    const float INV2PI = 0.15915494309189535f;
    const float MAGIC  = 12582912.0f;          // 1.5 * 2^23
    const float HI     = 6.2831855f;           // fl32(2*pi)
    const float LO     = (float)(6.283185307179586476925286766559
                                 - (double)6.2831855f);

    for (;;) {
        if (tid == 0) s_item = atomicAdd(&g_ctr, 1);
        __syncthreads();
        const int it = s_item;
        if (it >= NITEMS) break;               // uniform exit

        const int be    = it >> 5;
        const int chunk = it & 31;
        const int nact  = snact[be];
        const float* fp = sf + be * NOCT;
        const float* ap = sa + be * NOCT;

        // thread owns samples chunk*1024 + tid*4 + j  (j=0..3)
        const float tb = (float)(chunk * ITEM_SAMP + tid * 4 + 1);
        float tv0 = tb, tv1 = tb + 1.0f, tv2 = tb + 2.0f, tv3 = tb + 3.0f;

        float a0 = 0.0f, a1 = 0.0f, a2 = 0.0f, a3 = 0.0f;

        #pragma unroll 1
        for (int o = 0; o < nact; o++) {
            const float f = fp[o];             // broadcast LDS
            const float a = ap[o];

            float p0 = __fmul_rn(f, tv0);
            float p1 = __fmul_rn(f, tv1);
            float p2 = __fmul_rn(f, tv2);
            float p3 = __fmul_rn(f, tv3);

            float k0 = __fadd_rn(__fmaf_rn(p0, INV2PI, MAGIC), -MAGIC);
            float k1 = __fadd_rn(__fmaf_rn(p1, INV2PI, MAGIC), -MAGIC);
            float k2 = __fadd_rn(__fmaf_rn(p2, INV2PI, MAGIC), -MAGIC);
            float k3 = __fadd_rn(__fmaf_rn(p3, INV2PI, MAGIC), -MAGIC);

            float r0 = __fmaf_rn(k0, -LO, __fmaf_rn(k0, -HI, p0));
            float r1 = __fmaf_rn(k1, -LO, __fmaf_rn(k1, -HI, p1));
            float r2 = __fmaf_rn(k2, -LO, __fmaf_rn(k2, -HI, p2));
            float r3 = __fmaf_rn(k3, -LO, __fmaf_rn(k3, -HI, p3));

            a0 = __fmaf_rn(__sinf(r0), a, a0);
            a1 = __fmaf_rn(__sinf(r1), a, a1);
            a2 = __fmaf_rn(__sinf(r2), a, a2);
            a3 = __fmaf_rn(__sinf(r3), a, a3);
        }

        float4 w; w.x = a0; w.y = a1; w.z = a2; w.w = a3;
        ((float4*)(out + be * NSAMP + chunk * ITEM_SAMP))[tid] = w;

        // per-item max-abs
        float m = fmaxf(fmaxf(fabsf(a0), fabsf(a1)),
                        fmaxf(fabsf(a2), fabsf(a3)));
        #pragma unroll
        for (int off = 16; off > 0; off >>= 1)
            m = fmaxf(m, __shfl_xor_sync(0xFFFFFFFFu, m, off));
        if (lane == 0) wm[wrp] = m;
        __syncthreads();
        if (tid == 0) {
            float mm = wm[0];
            #pragma unroll
            for (int j = 1; j < TPB / 32; j++) mm = fmaxf(mm, wm[j]);
            g_wmax[it] = mm;
        }
        // loop-top: tid0 writes s_item only after its own work here; other
        // threads wait at the post-fetch __syncthreads before reading it.
    }
}

// ---------------------------------------------------------------------------
// Kernel B: reduce 32 chunk-maxes per be, normalize in place; also resets the
// work-queue counter for the next graph replay.
// ---------------------------------------------------------------------------
__global__ void __launch_bounds__(TPB)
norm_kernel(float4* __restrict__ out4) {
    const int be   = blockIdx.y;
    const int seg  = blockIdx.x;               // 0..15, each 512 float4
    const int tid  = threadIdx.x;
    const int lane = tid & 31;

    if (be == 0 && seg == 0 && tid == 0) g_ctr = 0;   // replay reset

    float v = g_wmax[be * 32 + lane];
    #pragma unroll
    for (int off = 16; off > 0; off >>= 1)
        v = fmaxf(v, __shfl_xor_sync(0xFFFFFFFFu, v, off));
    const float inv = 1.0f / (v + 1e-8f);

    float4* p = out4 + be * (NSAMP / 4) + seg * 512;
    float4 w0 = p[tid];
    float4 w1 = p[tid + TPB];
    w0.x *= inv; w0.y *= inv; w0.z *= inv; w0.w *= inv;
    w1.x *= inv; w1.y *= inv; w1.z *= inv; w1.w *= inv;
    p[tid]       = w0;
    p[tid + TPB] = w1;
}

extern "C" void kernel_launch(void* const* d_in, const int* in_sizes, int n_in,
                              void* d_out, int out_size) {
    const float* f0  = (const float*)d_in[0];
    const float* dec = (const float*)d_in[1];
    const float* sp  = (const float*)d_in[2];
    float* out = (float*)d_out;

    osc_kernel<<<1036, TPB>>>(f0, dec, sp, out);   // ~7 resident blocks/SM
    dim3 gB(16, BE);                               // 1024 blocks
    norm_kernel<<<gB, TPB>>>((float4*)out);
}

// round 6
// speedup vs baseline: 1.2488x; 1.2488x over previous
#include <cuda_runtime.h>
#include <math.h>

#define BE 64
#define NOCT 32
#define NSAMP 32768
#define TPB 256
#define ITEM_SAMP 2048
#define NITEMS (BE * NSAMP / ITEM_SAMP)   // 1024 work items
#define NBLK 592                          // ~4 resident blocks/SM
#define SPT 8

// Scratch (no allocation allowed). g_wmax slots each written exactly once per
// launch (unique queue claim). g_ctr: static 0 initially; reset by norm_kernel
// which always follows osc_kernel in-stream -> deterministic across replays.
__device__ float g_wmax[NITEMS];
__device__ int   g_ctr;

// ---------------------------------------------------------------------------
// Kernel A: oscillator bank, work-queue balanced, SPT=8 ILP.
// Phase-critical math replicates the reference's f32 rounding exactly:
// separate RN ops, sequential f32 cumsum for factors, fl32(f*t) phase,
// then exact 2-FMA Cody-Waite 2pi reduction + MUFU sin.
// ---------------------------------------------------------------------------
__global__ void __launch_bounds__(TPB)
osc_kernel(const float* __restrict__ f0_in,
           const float* __restrict__ dec_in,
           const float* __restrict__ sp_in,
           float* __restrict__ out) {
    __shared__ float sf[BE * NOCT];
    __shared__ float sa[BE * NOCT];
    __shared__ float s_ld[BE];
    __shared__ int   snact[BE];
    __shared__ int   s_item;
    __shared__ float wm[TPB / 32];

    const int tid  = threadIdx.x;
    const int lane = tid & 31;
    const int wrp  = tid >> 5;

    // ---- parallel per-block param table ----
    if (tid < BE) {
        const float MINF   = (float)(20.0 / 11025.0);
        const float FRANGE = (float)(3000.0 / 11025.0 - 20.0 / 11025.0);
        const float PI_F   = (float)3.14159265358979323846;
        const float RESF   = (float)((1.0 - 0.01) * 0.99);

        float f0  = fabsf(f0_in[tid]);
        float fsc = __fmul_rn(__fadd_rn(MINF, __fmul_rn(f0, FRANGE)), PI_F);
        float sp  = sp_in[tid];

        float x  = dec_in[tid];
        float s1 = 1.0f / (1.0f + expf(-x));
        float s2 = 1.0f / (1.0f + expf(-s1));
        float d  = __fadd_rn(0.01f, __fmul_rn(s2, RESF));
        s_ld[tid] = logf(__fadd_rn(d, 1e-12f));

        float fac = 0.0f;
        int nact = 0;
        #pragma unroll 1
        for (int o = 0; o < NOCT; o++) {
            fac = __fadd_rn(fac, sp);            // sequential f32 cumsum
            float f0s = __fmul_rn(fsc, fac);
            sf[tid * NOCT + o] = f0s;
            if (f0s < 1.0f) nact = o + 1;        // monotone -> prefix mask
        }
        snact[tid] = nact;
    }
    __syncthreads();
    // amplitudes: 2048 values across all 256 threads (amp errors don't
    // amplify with t -> direct (o+1)*ld + fast exp is safe)
    #pragma unroll
    for (int j = 0; j < BE * NOCT / TPB; j++) {
        int idx = tid + j * TPB;
        int o   = idx & (NOCT - 1);
        sa[idx] = __expf((float)(o + 1) * s_ld[idx >> 5]);
    }
    __syncthreads();

    const float INV2PI = 0.15915494309189535f;
    const float MAGIC  = 12582912.0f;            // 1.5 * 2^23
    const float HI     = 6.2831855f;             // fl32(2*pi)
    const float LO     = (float)(6.283185307179586476925286766559
                                 - (double)6.2831855f);

    for (;;) {
        if (tid == 0) s_item = atomicAdd(&g_ctr, 1);
        __syncthreads();
        const int it = s_item;
        __syncthreads();                          // protect s_item reuse
        if (it >= NITEMS) break;                  // uniform exit

        const int be    = it >> 4;                // 16 items per be
        const int chunk = it & 15;
        const int nact  = snact[be];
        const float* fp = sf + be * NOCT;
        const float* ap = sa + be * NOCT;

        // thread owns samples chunk*2048 + g*1024 + tid*4 + j
        const float tb = (float)(chunk * ITEM_SAMP + tid * 4 + 1);
        float tv[SPT];
        #pragma unroll
        for (int k = 0; k < SPT; k++)
            tv[k] = tb + (float)((k >> 2) * 1024 + (k & 3));

        float acc[SPT];
        #pragma unroll
        for (int k = 0; k < SPT; k++) acc[k] = 0.0f;

        #pragma unroll 1
        for (int o = 0; o < nact; o++) {
            const float f = fp[o];                // broadcast LDS
            const float a = ap[o];
            #pragma unroll
            for (int k = 0; k < SPT; k++) {
                float p  = __fmul_rn(f, tv[k]);   // reference fl32 phase
                float kk = __fadd_rn(__fmaf_rn(p, INV2PI, MAGIC), -MAGIC);
                float r  = __fmaf_rn(kk, -HI, p);
                r        = __fmaf_rn(kk, -LO, r); // exact CW reduction
                acc[k]   = __fmaf_rn(__sinf(r), a, acc[k]);
            }
        }

        float4* o4 = (float4*)(out + be * NSAMP + chunk * ITEM_SAMP);
        #pragma unroll
        for (int g = 0; g < 2; g++) {
            float4 w;
            w.x = acc[g * 4 + 0];
            w.y = acc[g * 4 + 1];
            w.z = acc[g * 4 + 2];
            w.w = acc[g * 4 + 3];
            o4[g * TPB + tid] = w;
        }

        float m = 0.0f;
        #pragma unroll
        for (int k = 0; k < SPT; k++) m = fmaxf(m, fabsf(acc[k]));
        #pragma unroll
        for (int off = 16; off > 0; off >>= 1)
            m = fmaxf(m, __shfl_xor_sync(0xFFFFFFFFu, m, off));
        if (lane == 0) wm[wrp] = m;
        __syncthreads();
        if (tid == 0) {
            float mm = wm[0];
            #pragma unroll
            for (int j = 1; j < TPB / 32; j++) mm = fmaxf(mm, wm[j]);
            g_wmax[it] = mm;
        }
    }
}

// ---------------------------------------------------------------------------
// Kernel B: reduce 16 item-maxes per be, normalize in place (4x float4 MLP);
// resets the work-queue counter for the next replay.
// ---------------------------------------------------------------------------
__global__ void __launch_bounds__(TPB)
norm_kernel(float4* __restrict__ out4) {
    const int be   = blockIdx.y;
    const int seg  = blockIdx.x;                  // 0..7, each 1024 float4
    const int tid  = threadIdx.x;
    const int lane = tid & 31;

    if (be == 0 && seg == 0 && tid == 0) g_ctr = 0;   // replay reset

    float v = g_wmax[be * 16 + (lane & 15)];
    #pragma unroll
    for (int off = 8; off > 0; off >>= 1)
        v = fmaxf(v, __shfl_xor_sync(0xFFFFFFFFu, v, off));
    const float inv = 1.0f / (v + 1e-8f);

    float4* p = out4 + be * (NSAMP / 4) + seg * 1024;
    float4 w0 = p[tid];
    float4 w1 = p[tid + TPB];
    float4 w2 = p[tid + 2 * TPB];
    float4 w3 = p[tid + 3 * TPB];
    w0.x *= inv; w0.y *= inv; w0.z *= inv; w0.w *= inv;
    w1.x *= inv; w1.y *= inv; w1.z *= inv; w1.w *= inv;
    w2.x *= inv; w2.y *= inv; w2.z *= inv; w2.w *= inv;
    w3.x *= inv; w3.y *= inv; w3.z *= inv; w3.w *= inv;
    p[tid]           = w0;
    p[tid + TPB]     = w1;
    p[tid + 2 * TPB] = w2;
    p[tid + 3 * TPB] = w3;
}

extern "C" void kernel_launch(void* const* d_in, const int* in_sizes, int n_in,
                              void* d_out, int out_size) {
    const float* f0  = (const float*)d_in[0];
    const float* dec = (const float*)d_in[1];
    const float* sp  = (const float*)d_in[2];
    float* out = (float*)d_out;

    osc_kernel<<<NBLK, TPB>>>(f0, dec, sp, out);
    dim3 gB(8, BE);                               // 512 blocks
    norm_kernel<<<gB, TPB>>>((float4*)out);
}